// round 16
// baseline (speedup 1.0000x reference)
#include <cuda_runtime.h>
#include <cstdint>

#define NN 8192
#define SCORE_TH 0.5f
#define W64 (NN / 64)
#define GRID 128
#define BT   1024

typedef unsigned long long u64;

// Global scratch (no allocations allowed; __device__ globals are zero-init)
__device__ float4        g_boxes_s[NN];
__device__ float         g_conf_s[NN];
__device__ float         g_area_s[NN];
__device__ unsigned char g_valid_s[NN];
__device__ u64           g_supT[W64][NN];   // transposed suppression bitmap
__device__ unsigned int  g_key[NN];
__device__ unsigned int  g_maxbits;
__device__ unsigned int  g_bar[4];
__device__ unsigned int  g_exit;

// Replay-safe grid barrier: blocks <= SM count and 1 block/SM resources ->
// all resident -> spin cannot deadlock. Counters reset by last exiter.
__device__ __forceinline__ void grid_barrier(int id) {
    __syncthreads();
    if (threadIdx.x == 0) {
        __threadfence();                         // release prior writes
        atomicAdd(&g_bar[id], 1u);
        while (*((volatile unsigned int*)&g_bar[id]) < GRID) { }
        __threadfence();                         // acquire remote writes
    }
    __syncthreads();
}

__global__ void __launch_bounds__(BT, 1)
nms_mega(const float* __restrict__ in, float* __restrict__ out) {
    __shared__ __align__(16) unsigned char su[44288];   // phase-overlaid smem
    __shared__ int s_i_unused;                          // (keep layout simple)
    const int tid = threadIdx.x;
    const int bid = blockIdx.x;

    // ---------- P0: zero output + global conf max ----------
    {
        float4* out4 = (float4*)out;
        for (int i = bid * BT + tid; i < (NN * 5) / 4; i += GRID * BT)
            out4[i] = make_float4(0.f, 0.f, 0.f, 0.f);
        float m = 0.0f;                                  // conf >= 0
        for (int j = bid * BT + tid; j < NN; j += GRID * BT)
            m = fmaxf(m, in[j * 5 + 4]);
        #pragma unroll
        for (int o = 16; o; o >>= 1)
            m = fmaxf(m, __shfl_xor_sync(0xFFFFFFFFu, m, o));
        if ((tid & 31) == 0 && m > 0.0f)
            atomicMax(&g_maxbits, __float_as_uint(m));   // monotone bits
    }
    grid_barrier(0);

    // ---------- P1: keys (computed ONCE; bit-exact vs jnp) ----------
    {
        const float mx = __uint_as_float(*((volatile unsigned int*)&g_maxbits));
        for (int j = bid * BT + tid; j < NN; j += GRID * BT)
            g_key[j] = ~__float_as_uint(__fdiv_rn(in[j * 5 + 4], mx));
    }
    grid_barrier(1);

    // ---------- P2: stable rank by counting (stable argsort(-conf)) ----------
    if (bid < 128) {
        unsigned int* key = (unsigned int*)su;           // 32 KB
        int* spart = (int*)(su + 32768);                 // 15*64*4 = 3840
        #pragma unroll
        for (int k = 0; k < NN / BT; k++)
            key[tid + k * BT] = g_key[tid + k * BT];     // coalesced
        __syncthreads();

        const int e = tid & 63;                          // element 0..63
        const int q = tid >> 6;                          // slice 0..15 x 512
        const int i = bid * 64 + e;
        const unsigned int Ki = key[i];
        const int lo = q * 512, up = lo + 512;

        int r = 0;
        const int b1 = min(up, max(lo, i));              // j<i: count <=
        #pragma unroll 8
        for (int j = lo; j < b1; j++) r += (key[j] <= Ki) ? 1 : 0;
        const int a2 = max(lo, min(up, i + 1));          // j>i: count <
        #pragma unroll 8
        for (int j = a2; j < up; j++) r += (key[j] < Ki) ? 1 : 0;

        if (q > 0) spart[(q - 1) * 64 + e] = r;
        __syncthreads();

        if (q == 0) {
            int rank = r;
            #pragma unroll
            for (int t = 0; t < 15; t++) rank += spart[t * 64 + e];
            const float* bp = in + i * 5;
            float cx = bp[0], cy = bp[1], w = bp[2], h = bp[3];
            float hw = __fmul_rn(w, 0.5f);
            float hh = __fmul_rn(h, 0.5f);
            float x1 = __fsub_rn(cx, hw), y1 = __fsub_rn(cy, hh);
            float x2 = __fadd_rn(cx, hw), y2 = __fadd_rn(cy, hh);
            float conf = __uint_as_float(~Ki);
            g_boxes_s[rank] = make_float4(x1, y1, x2, y2);
            g_conf_s[rank]  = conf;
            g_area_s[rank]  = __fmul_rn(__fsub_rn(x2, x1), __fsub_rn(y2, y1));
            g_valid_s[rank] = (conf >= SCORE_TH) ? 1 : 0;
        }
    }
    grid_barrier(2);

    // ---------- P3: suppression bitmap (256j x 4 i-slices per tile) ----------
    {
        float4* sb = (float4*)su;                        // 4 KB
        float*  sa = (float*)(su + 4096);                // 1 KB
        for (int t = bid; t < 528; t += GRID) {
            int tj = 0;                                  // triangular decode
            while ((tj + 1) * (tj + 2) / 2 <= t) tj++;
            int ti = t - tj * (tj + 1) / 2;              // ti <= tj
            int j0 = tj * 256, i0 = ti * 256;
            if (g_valid_s[j0] && g_valid_s[i0]) {        // block-uniform
                if (tid < 256) {
                    sb[tid] = g_boxes_s[i0 + tid];
                    sa[tid] = g_area_s[i0 + tid];
                }
                __syncthreads();
                const int jj = j0 + (tid & 255);
                const int s  = tid >> 8;                 // i-slice 0..3
                const int iend = min(jj - i0, 256);
                const int t0 = s * 64, t1 = min(iend, t0 + 64);
                if (g_valid_s[jj] && t1 > t0) {
                    const float4 bj = g_boxes_s[jj];
                    const float  aj = g_area_s[jj];
                    u64 mm = 0;
                    for (int tt = t0; tt < t1; tt++) {
                        float4 bi = sb[tt];
                        float ix1 = fmaxf(bi.x, bj.x);
                        float iy1 = fmaxf(bi.y, bj.y);
                        float ix2 = fminf(bi.z, bj.z);
                        float iy2 = fminf(bi.w, bj.w);
                        float iw  = fmaxf(__fsub_rn(ix2, ix1), 0.0f);
                        float ih  = fmaxf(__fsub_rn(iy2, iy1), 0.0f);
                        float inter = __fmul_rn(iw, ih);
                        float uni   = __fsub_rn(__fadd_rn(sa[tt], aj), inter);
                        // iou > 0.5  <=>  inter > 0.5*max(uni, 1e-9)
                        u64 hit = (inter > __fmul_rn(0.5f, fmaxf(uni, 1e-9f)))
                                      ? 1ull : 0ull;
                        mm |= hit << (tt - t0);
                    }
                    g_supT[(i0 >> 6) + s][jj] = mm;      // unique writer
                }
                __syncthreads();
            }
        }
    }
    grid_barrier(3);

    // ---------- P4: exact greedy resolve (block 0; R15-proven logic) ----------
    if (bid == 0) {
        u64* sm_   = (u64*)su;                           // 32 KB intra masks
        u64* sA    = (u64*)(su + 32768);                 //  8 KB partials
        u64* keepw = (u64*)(su + 40960);                 //  1 KB keep bitmap
        unsigned char* deadb = su + 41984;               //  512 B
        int* scnt = (int*)(su + 42512);                  //  128 B
        int* psM  = (int*)(su + 42640);

        for (int k = tid; k < W64; k += BT) keepw[k] = 0;
        int cnt = 0;
        #pragma unroll
        for (int k = 0; k < NN / BT; k++)
            cnt += (g_valid_s[tid + k * BT] != 0) ? 1 : 0;
        #pragma unroll
        for (int o = 16; o; o >>= 1)
            cnt += __shfl_xor_sync(0xFFFFFFFFu, cnt, o);
        if ((tid & 31) == 0) scnt[tid >> 5] = cnt;
        __syncthreads();
        if (tid == 0) {
            int s = 0;
            #pragma unroll
            for (int w = 0; w < 32; w++) s += scnt[w];
            *psM = s;
        }
        __syncthreads();
        const int M = *psM;

        const int jl = tid & 511;
        const int sl = tid >> 9;                         // slice 0..1

        for (int b = 0; b < 8; b++) {
            if (b * 512 >= M) break;                     // uniform
            const int j = b * 512 + jl;

            // A: cross gather vs FINAL earlier keeps (coalesced)
            u64 acc = 0;
            for (int gg = sl; gg < 8 * b; gg += 2)
                acc |= g_supT[gg][j] & keepw[gg];
            sA[sl * 512 + jl] = acc;

            // B: stage intra mask words (coalesced)
            #pragma unroll
            for (int k = 0; k < 4; k++) {
                int idx = k * BT + tid;
                sm_[idx] = g_supT[8 * b + (idx >> 9)][b * 512 + (idx & 511)];
            }
            __syncthreads();

            if (tid < 512) {
                bool dead = ((sA[tid] | sA[512 + tid]) != 0ull) ||
                            (g_valid_s[b * 512 + tid] == 0);
                deadb[tid] = dead ? 1 : 0;
            }
            __syncthreads();

            // C: warp 0 resolves 8 words via bit-parallel Jacobi (exact)
            if (tid < 32) {
                const int lane = tid;
                u64 kw[8];
                #pragma unroll
                for (int w = 0; w < 8; w++) {
                    const int rlo = w * 64 + lane;
                    const int rhi = rlo + 32;
                    u64 suplo = 0, suphi = 0;
                    #pragma unroll
                    for (int w2 = 0; w2 < 7; w2++) {
                        if (w2 < w) {
                            suplo |= sm_[w2 * 512 + rlo] & kw[w2];
                            suphi |= sm_[w2 * 512 + rhi] & kw[w2];
                        }
                    }
                    bool al_lo = (deadb[rlo] == 0) && (suplo == 0ull);
                    bool al_hi = (deadb[rhi] == 0) && (suphi == 0ull);
                    u64 rm_lo = (lane > 0) ? sm_[w * 512 + rlo] : 0ull;
                    u64 rm_hi = sm_[w * 512 + rhi];

                    unsigned int candl = __ballot_sync(0xFFFFFFFFu, al_lo);
                    unsigned int candh = __ballot_sync(0xFFFFFFFFu, al_hi);
                    u64 cand = (u64)candl | ((u64)candh << 32);
                    u64 k = cand;
                    while (true) {                       // settles in chain depth
                        bool s_lo = (rm_lo & k) != 0ull;
                        bool s_hi = (rm_hi & k) != 0ull;
                        unsigned int nl = __ballot_sync(0xFFFFFFFFu, !s_lo);
                        unsigned int nh = __ballot_sync(0xFFFFFFFFu, !s_hi);
                        u64 nk = cand & ((u64)nl | ((u64)nh << 32));
                        if (nk == k) break;
                        k = nk;
                    }
                    kw[w] = k;                           // uniform across lanes
                    if (lane == 0) keepw[8 * b + w] = k;
                }
            }
            __syncthreads();
        }

        // emit kept rows (P0 zero-filled)
        #pragma unroll
        for (int k = 0; k < NN / BT; k++) {
            int p = tid + k * BT;
            if ((keepw[p >> 6] >> (p & 63)) & 1ull) {
                float4 b = g_boxes_s[p];
                float* o = out + p * 5;
                o[0] = b.x; o[1] = b.y; o[2] = b.z; o[3] = b.w;
                o[4] = g_conf_s[p];
            }
        }
    }

    // ---------- exit: last block resets barrier state for next replay ----------
    __syncthreads();
    if (tid == 0) {
        __threadfence();
        unsigned int v = atomicAdd(&g_exit, 1u);
        if (v == GRID - 1) {                             // everyone is past
            g_bar[0] = 0; g_bar[1] = 0; g_bar[2] = 0; g_bar[3] = 0;
            g_maxbits = 0;
            g_exit = 0;
            __threadfence();
        }
    }
}

// ---------------------------------------------------------------------------
extern "C" void kernel_launch(void* const* d_in, const int* in_sizes, int n_in,
                              void* d_out, int out_size) {
    const float* in = (const float*)d_in[0];
    float* out = (float*)d_out;
    nms_mega<<<GRID, BT>>>(in, out);                     // single graph node
}